// round 1
// baseline (speedup 1.0000x reference)
#include <cuda_runtime.h>
#include <math.h>

#define NN   100000
#define EE   1600000
#define DIN  256
#define DH   128
#define HOP  5

// ---------------- scratch (static device globals; no allocations) ----------------
__device__ __align__(256) float g_xp [NN * DH];
__device__ __align__(256) float g_xa [NN * DH];
__device__ __align__(256) float g_hp0[NN * DH];
__device__ __align__(256) float g_hp1[NN * DH];
__device__ __align__(256) float g_ha0[NN * DH];
__device__ __align__(256) float g_ha1[NN * DH];
__device__ int   g_cnt   [4 * NN];
__device__ int   g_rowptr[4 * (NN + 1)];
__device__ int   g_cursor[4 * NN];
__device__ __align__(256) int   g_ecol[4 * (size_t)EE];
__device__ __align__(256) float g_eval[4 * (size_t)EE];

// ---------------- input projection GEMM: Y[n,128] = relu(X[n,256] @ W + b) -------
// BM=64, BN=128 (full), BK=32, 256 threads, 8x4 microtile per thread.
__global__ __launch_bounds__(256) void gemm_relu_kernel(
    const float* __restrict__ X, const float* __restrict__ W,
    const float* __restrict__ bias, float* __restrict__ Y)
{
    __shared__ float As[32][65];    // [k][m], padded
    __shared__ float Bs[32][128];

    int tid = threadIdx.x;
    int block_row = blockIdx.x * 64;
    int tc = tid & 31;   // 32 col-groups of 4
    int tr = tid >> 5;   // 8 row-groups of 8

    float acc[8][4];
#pragma unroll
    for (int i = 0; i < 8; ++i)
#pragma unroll
        for (int j = 0; j < 4; ++j) acc[i][j] = 0.f;

    for (int k0 = 0; k0 < DIN; k0 += 32) {
        // load A tile: 64 rows x 32 k = 512 float4, 2 per thread
#pragma unroll
        for (int f = tid; f < 512; f += 256) {
            int r  = f >> 3;
            int kq = f & 7;
            int gr = block_row + r;
            float4 v = make_float4(0.f, 0.f, 0.f, 0.f);
            if (gr < NN)
                v = *(const float4*)(X + (size_t)gr * DIN + k0 + kq * 4);
            As[kq * 4 + 0][r] = v.x;
            As[kq * 4 + 1][r] = v.y;
            As[kq * 4 + 2][r] = v.z;
            As[kq * 4 + 3][r] = v.w;
        }
        // load B tile: 32 k x 128 = 1024 float4, 4 per thread
#pragma unroll
        for (int f = tid; f < 1024; f += 256) {
            int kk = f >> 5;
            int cq = f & 31;
            *(float4*)&Bs[kk][cq * 4] =
                *(const float4*)(W + (size_t)(k0 + kk) * DH + cq * 4);
        }
        __syncthreads();

#pragma unroll
        for (int kk = 0; kk < 32; ++kk) {
            float4 b = *(float4*)&Bs[kk][tc * 4];
            float a[8];
#pragma unroll
            for (int i = 0; i < 8; ++i) a[i] = As[kk][tr * 8 + i];
#pragma unroll
            for (int i = 0; i < 8; ++i) {
                acc[i][0] = fmaf(a[i], b.x, acc[i][0]);
                acc[i][1] = fmaf(a[i], b.y, acc[i][1]);
                acc[i][2] = fmaf(a[i], b.z, acc[i][2]);
                acc[i][3] = fmaf(a[i], b.w, acc[i][3]);
            }
        }
        __syncthreads();
    }

    float4 bb = *(const float4*)(bias + tc * 4);
#pragma unroll
    for (int i = 0; i < 8; ++i) {
        int gr = block_row + tr * 8 + i;
        if (gr < NN) {
            float4 o;
            o.x = fmaxf(acc[i][0] + bb.x, 0.f);
            o.y = fmaxf(acc[i][1] + bb.y, 0.f);
            o.z = fmaxf(acc[i][2] + bb.z, 0.f);
            o.w = fmaxf(acc[i][3] + bb.w, 0.f);
            *(float4*)(Y + (size_t)gr * DH + tc * 4) = o;
        }
    }
}

// ---------------- CSR build ----------------
__global__ void zero_counts_kernel(int* __restrict__ c)
{
    int i = blockIdx.x * 256 + threadIdx.x;
    if (i < 4 * NN) c[i] = 0;
}

__global__ void hist_kernel(const int* __restrict__ rows, int* __restrict__ cnt)
{
    int e = blockIdx.x * 256 + threadIdx.x;
    if (e < EE) atomicAdd(&cnt[rows[e]], 1);
}

// one block (1024 thr) per edge type: exclusive scan of cnt -> rowptr
__global__ void scan_kernel(const int* __restrict__ cnt, int* __restrict__ rowptr)
{
    const int* c  = cnt + blockIdx.x * NN;
    int*       rp = rowptr + blockIdx.x * (NN + 1);
    __shared__ int sh[1024];
    __shared__ int carry;
    int tid = threadIdx.x;
    if (tid == 0) carry = 0;
    __syncthreads();
    for (int base = 0; base < NN; base += 1024) {
        int i = base + tid;
        int v = (i < NN) ? c[i] : 0;
        sh[tid] = v;
        __syncthreads();
        for (int off = 1; off < 1024; off <<= 1) {
            int t = (tid >= off) ? sh[tid - off] : 0;
            __syncthreads();
            sh[tid] += t;
            __syncthreads();
        }
        if (i < NN) rp[i] = carry + sh[tid] - v;   // exclusive
        __syncthreads();
        if (tid == 0) carry += sh[1023];
        __syncthreads();
    }
    if (tid == 0) rp[NN] = carry;
}

__global__ void init_cursor_kernel(const int* __restrict__ rowptr, int* __restrict__ cursor)
{
    int i = blockIdx.x * 256 + threadIdx.x;
    if (i < 4 * NN) {
        int t = i / NN, r = i - t * NN;
        cursor[i] = rowptr[t * (NN + 1) + r];
    }
}

__global__ void scatter_kernel(const int* __restrict__ rows, const int* __restrict__ cols,
                               const float* __restrict__ vals,
                               int* __restrict__ cursor,
                               int* __restrict__ ecol, float* __restrict__ eval)
{
    int e = blockIdx.x * 256 + threadIdx.x;
    if (e < EE) {
        int r = rows[e];
        int p = atomicAdd(&cursor[r], 1);
        ecol[p] = cols[e];
        eval[p] = vals[e];
    }
}

// ---------------- fused dual-edge-type SpMM + diag residual + weighted combine ----
__device__ __forceinline__ float4 gather_row(
    const int* __restrict__ rp, const int* __restrict__ ec,
    const float* __restrict__ ev, const float* __restrict__ h,
    int r, int col4)
{
    int s = rp[r];
    int e = rp[r + 1];
    float ax = 0.f, ay = 0.f, az = 0.f, aw = 0.f;
    int i = s;
    for (; i + 4 <= e; i += 4) {
        int   c0 = ec[i + 0], c1 = ec[i + 1], c2 = ec[i + 2], c3 = ec[i + 3];
        float v0 = ev[i + 0], v1 = ev[i + 1], v2 = ev[i + 2], v3 = ev[i + 3];
        float4 h0 = *(const float4*)(h + (size_t)c0 * DH + col4);
        float4 h1 = *(const float4*)(h + (size_t)c1 * DH + col4);
        float4 h2 = *(const float4*)(h + (size_t)c2 * DH + col4);
        float4 h3 = *(const float4*)(h + (size_t)c3 * DH + col4);
        ax = fmaf(v0, h0.x, fmaf(v1, h1.x, fmaf(v2, h2.x, fmaf(v3, h3.x, ax))));
        ay = fmaf(v0, h0.y, fmaf(v1, h1.y, fmaf(v2, h2.y, fmaf(v3, h3.y, ay))));
        az = fmaf(v0, h0.z, fmaf(v1, h1.z, fmaf(v2, h2.z, fmaf(v3, h3.z, az))));
        aw = fmaf(v0, h0.w, fmaf(v1, h1.w, fmaf(v2, h2.w, fmaf(v3, h3.w, aw))));
    }
    for (; i < e; ++i) {
        int   c = ec[i];
        float v = ev[i];
        float4 hv = *(const float4*)(h + (size_t)c * DH + col4);
        ax = fmaf(v, hv.x, ax);
        ay = fmaf(v, hv.y, ay);
        az = fmaf(v, hv.z, az);
        aw = fmaf(v, hv.w, aw);
    }
    return make_float4(ax, ay, az, aw);
}

__global__ __launch_bounds__(256) void spmm2_kernel(
    const int* __restrict__ rpA, const int* __restrict__ ecA,
    const float* __restrict__ evA, const float* __restrict__ hA,
    const int* __restrict__ rpB, const int* __restrict__ ecB,
    const float* __restrict__ evB, const float* __restrict__ hB,
    const float* __restrict__ dA, const float* __restrict__ dB,
    const float* __restrict__ x,
    const float* __restrict__ lw, int lwoff,
    float* __restrict__ out)
{
    int warp = (blockIdx.x * 256 + threadIdx.x) >> 5;
    if (warp >= NN) return;
    int lane = threadIdx.x & 31;
    int col4 = lane * 4;

    // softmax over the two layer weights
    float l0 = lw[lwoff], l1 = lw[lwoff + 1];
    float mx = fmaxf(l0, l1);
    float e0 = __expf(l0 - mx), e1 = __expf(l1 - mx);
    float inv = 1.0f / (e0 + e1);
    float w0 = e0 * inv, w1 = e1 * inv;

    float4 aA = gather_row(rpA, ecA, evA, hA, warp, col4);
    float4 aB = gather_row(rpB, ecB, evB, hB, warp, col4);

    float4 xv = *(const float4*)(x + (size_t)warp * DH + col4);
    float  da = dA[warp], db = dB[warp];

    float4 r;
    r.x = w0 * (aA.x + da * xv.x) + w1 * (aB.x + db * xv.x);
    r.y = w0 * (aA.y + da * xv.y) + w1 * (aB.y + db * xv.y);
    r.z = w0 * (aA.z + da * xv.z) + w1 * (aB.z + db * xv.z);
    r.w = w0 * (aA.w + da * xv.w) + w1 * (aB.w + db * xv.w);
    *(float4*)(out + (size_t)warp * DH + col4) = r;
}

// ---------------- output GEMM: Y[n,8] = H[n,128] @ W2[128,8] + b2 -----------------
__global__ __launch_bounds__(256) void out_gemm_kernel(
    const float* __restrict__ H, const float* __restrict__ W2,
    const float* __restrict__ b2, float* __restrict__ Y)
{
    __shared__ float Ws[8 * 128];   // transposed: Ws[j*128 + k] = W2[k*8 + j]
    int tid = threadIdx.x;
#pragma unroll
    for (int i = tid; i < 1024; i += 256) {
        int k = i >> 3, j = i & 7;
        Ws[j * 128 + k] = W2[i];
    }
    __syncthreads();

    int warp = (blockIdx.x * 256 + tid) >> 5;
    if (warp >= NN) return;
    int lane = tid & 31;
    int k4 = lane * 4;

    float4 h = *(const float4*)(H + (size_t)warp * DH + k4);
    float s[8];
#pragma unroll
    for (int j = 0; j < 8; ++j) {
        s[j] = h.x * Ws[j * 128 + k4 + 0]
             + h.y * Ws[j * 128 + k4 + 1]
             + h.z * Ws[j * 128 + k4 + 2]
             + h.w * Ws[j * 128 + k4 + 3];
    }
#pragma unroll
    for (int off = 16; off; off >>= 1)
#pragma unroll
        for (int j = 0; j < 8; ++j)
            s[j] += __shfl_xor_sync(0xffffffffu, s[j], off);

    if (lane == 0) {
        float4 o0 = make_float4(s[0] + b2[0], s[1] + b2[1], s[2] + b2[2], s[3] + b2[3]);
        float4 o1 = make_float4(s[4] + b2[4], s[5] + b2[5], s[6] + b2[6], s[7] + b2[7]);
        *(float4*)(Y + (size_t)warp * 8)     = o0;
        *(float4*)(Y + (size_t)warp * 8 + 4) = o1;
    }
}

// ---------------- launch ----------------
extern "C" void kernel_launch(void* const* d_in, const int* in_sizes, int n_in,
                              void* d_out, int out_size)
{
    const float* x_paper  = (const float*)d_in[0];
    const float* x_author = (const float*)d_in[1];
    const int*   rows[4] = { (const int*)d_in[2],  (const int*)d_in[6],
                             (const int*)d_in[10], (const int*)d_in[14] };
    const int*   cols[4] = { (const int*)d_in[3],  (const int*)d_in[7],
                             (const int*)d_in[11], (const int*)d_in[15] };
    const float* vals[4] = { (const float*)d_in[4],  (const float*)d_in[8],
                             (const float*)d_in[12], (const float*)d_in[16] };
    const float* diag[4] = { (const float*)d_in[5],  (const float*)d_in[9],
                             (const float*)d_in[13], (const float*)d_in[17] };
    const float* W1p = (const float*)d_in[18];
    const float* b1p = (const float*)d_in[19];
    const float* W1a = (const float*)d_in[20];
    const float* b1a = (const float*)d_in[21];
    const float* W2  = (const float*)d_in[22];
    const float* b2  = (const float*)d_in[23];
    const float* lw  = (const float*)d_in[24];
    float* out = (float*)d_out;

    float *xp, *xa, *hp0, *hp1, *ha0, *ha1, *evalp;
    int *cnt, *rowptr, *cursor, *ecol;
    cudaGetSymbolAddress((void**)&xp,     g_xp);
    cudaGetSymbolAddress((void**)&xa,     g_xa);
    cudaGetSymbolAddress((void**)&hp0,    g_hp0);
    cudaGetSymbolAddress((void**)&hp1,    g_hp1);
    cudaGetSymbolAddress((void**)&ha0,    g_ha0);
    cudaGetSymbolAddress((void**)&ha1,    g_ha1);
    cudaGetSymbolAddress((void**)&cnt,    g_cnt);
    cudaGetSymbolAddress((void**)&rowptr, g_rowptr);
    cudaGetSymbolAddress((void**)&cursor, g_cursor);
    cudaGetSymbolAddress((void**)&ecol,   g_ecol);
    cudaGetSymbolAddress((void**)&evalp,  g_eval);

    // 1. input projections
    const int gemm_blocks = (NN + 63) / 64;
    gemm_relu_kernel<<<gemm_blocks, 256>>>(x_paper,  W1p, b1p, xp);
    gemm_relu_kernel<<<gemm_blocks, 256>>>(x_author, W1a, b1a, xa);

    // 2. CSR build (amortized over all 5 hops)
    zero_counts_kernel<<<(4 * NN + 255) / 256, 256>>>(cnt);
    const int eblocks = (EE + 255) / 256;
    for (int t = 0; t < 4; ++t)
        hist_kernel<<<eblocks, 256>>>(rows[t], cnt + t * NN);
    scan_kernel<<<4, 1024>>>(cnt, rowptr);
    init_cursor_kernel<<<(4 * NN + 255) / 256, 256>>>(rowptr, cursor);
    for (int t = 0; t < 4; ++t)
        scatter_kernel<<<eblocks, 256>>>(rows[t], cols[t], vals[t],
                                         cursor + t * NN,
                                         ecol + (size_t)t * EE,
                                         evalp + (size_t)t * EE);

    // 3. hop loop (paper update, then author update using fresh h_p)
    const float* hp = xp;
    const float* ha = xa;
    float* hpB[2] = { hp0, hp1 };
    float* haB[2] = { ha0, ha1 };
    const int spmm_blocks = (NN * 32 + 255) / 256;   // warp per row
    for (int i = 0; i < HOP; ++i) {
        float* nhp = hpB[i & 1];
        spmm2_kernel<<<spmm_blocks, 256>>>(
            rowptr + 0 * (NN + 1), ecol + 0 * (size_t)EE, evalp + 0 * (size_t)EE, hp,
            rowptr + 1 * (NN + 1), ecol + 1 * (size_t)EE, evalp + 1 * (size_t)EE, ha,
            diag[0], diag[1], xp, lw, i * 4 + 0, nhp);
        float* nha = haB[i & 1];
        spmm2_kernel<<<spmm_blocks, 256>>>(
            rowptr + 2 * (NN + 1), ecol + 2 * (size_t)EE, evalp + 2 * (size_t)EE, nhp,
            rowptr + 3 * (NN + 1), ecol + 3 * (size_t)EE, evalp + 3 * (size_t)EE, ha,
            diag[2], diag[3], xa, lw, i * 4 + 2, nha);
        hp = nhp;
        ha = nha;
    }

    // 4. output projection
    out_gemm_kernel<<<spmm_blocks, 256>>>(hp, W2, b2, out);
}